// round 12
// baseline (speedup 1.0000x reference)
#include <cuda_runtime.h>
#include <cuda_bf16.h>
#include <cstdint>
#include <math.h>

#define Bb 64
#define Tt 256
#define Hh 768
#define KB 16

// ---------------- packed f32x2 helpers ---------------------------------------
__device__ __forceinline__ void ffma2(uint64_t& d, uint64_t a, uint64_t b) {
    asm("fma.rn.f32x2 %0, %1, %2, %0;" : "+l"(d) : "l"(a), "l"(b));
}
__device__ __forceinline__ uint64_t bcast2(float x) {
    uint64_t r;
    asm("mov.b64 %0, {%1, %1};" : "=l"(r) : "f"(x));
    return r;
}
__device__ __forceinline__ void unpack2(uint64_t v, float& lo, float& hi) {
    asm("mov.b64 {%0, %1}, %2;" : "=f"(lo), "=f"(hi) : "l"(v));
}
union F4U2 { float4 f; uint64_t u[2]; };

// ---------------- bf16 mma helpers -------------------------------------------
__device__ __forceinline__ uint32_t pack2bf(__nv_bfloat16 f0, __nv_bfloat16 f1) {
    __nv_bfloat162 h; h.x = f0; h.y = f1;
    return *reinterpret_cast<uint32_t*>(&h);
}
__device__ __forceinline__ void mma16816(float* c, const uint32_t* a, uint32_t b0, uint32_t b1) {
    asm("mma.sync.aligned.m16n8k16.row.col.f32.bf16.bf16.f32 "
        "{%0,%1,%2,%3}, {%4,%5,%6,%7}, {%8,%9}, {%0,%1,%2,%3};"
        : "+f"(c[0]), "+f"(c[1]), "+f"(c[2]), "+f"(c[3])
        : "r"(a[0]), "r"(a[1]), "r"(a[2]), "r"(a[3]), "r"(b0), "r"(b1));
}

// ---------------- scratch (static device globals; no allocation) -------------
__device__ float g_whqT[(size_t)Bb*Tt*Tt];   // whqT[b][i][j] = whq[b][j][i]
__device__ float g_whp [(size_t)Bb*Tt*Tt];
__device__ float g_pb  [(size_t)Bb*Tt*Hh];
__device__ float g_Sb  [(size_t)Bb*Tt*Tt];
__device__ float g_Sd  [(size_t)Bb*Tt*Tt];
__device__ float g_P   [(size_t)4*Bb*Tt*Tt];
__device__ float g_qWm[Bb*Tt];
__device__ float g_pWm[Bb*Tt];

// ---------------- K0: qWm[b,t] = q[b,t,:]@Wm ; pWm likewise ------------------
__global__ void k_vec(const float* __restrict__ q, const float* __restrict__ p,
                      const float* __restrict__ Wm) {
    int b = blockIdx.y, t = blockIdx.x, tid = threadIdx.x;
    const float* qr = q + ((size_t)b*Tt + t)*Hh;
    const float* pr = p + ((size_t)b*Tt + t)*Hh;
    float sq = 0.f, sp = 0.f;
    for (int h = tid; h < Hh; h += 256) {
        float w = Wm[h];
        sq += qr[h]*w; sp += pr[h]*w;
    }
    for (int o = 16; o; o >>= 1) {
        sq += __shfl_down_sync(0xffffffffu, sq, o);
        sp += __shfl_down_sync(0xffffffffu, sp, o);
    }
    __shared__ float ssq[8], ssp[8];
    int w = tid >> 5, l = tid & 31;
    if (!l) { ssq[w] = sq; ssp[w] = sp; }
    __syncthreads();
    if (tid == 0) {
        float a = 0.f, c = 0.f;
        for (int i = 0; i < 8; i++) { a += ssq[i]; c += ssp[i]; }
        g_qWm[b*Tt + t] = a;
        g_pWm[b*Tt + t] = c;
    }
}

// ======== tensor-core 128x128 batched GEMM (bf16 split, fp32 accum) ==========
// C[z] = A[z](MxK) @ W[z](KxN); A row-major pitch lda; W row-major pitch N.
// z batch: A += z*aStr, W += (z & wMask)*wStr, C += z*cStr.
// trans!=0 -> store C[n*Tt + m].
// Split: x = hi + lo (bf16 each); D = Ah*Bh + Ah*Bl + Al*Bh (fp32 accum).
#define PW 20   // smem row pitch in 32-bit words (40 bf16) — conflict-free frag reads
__global__ void __launch_bounds__(256, 2) gemm128t(
    const float* __restrict__ A, size_t aStr, int lda,
    const float* __restrict__ W, size_t wStr, int wMask, int N,
    float* __restrict__ C, size_t cStr, int K, int trans) {
    __shared__ __nv_bfloat16 Ah[128][2*PW], Al[128][2*PW];
    __shared__ __nv_bfloat16 Bh[128][2*PW], Bl[128][2*PW];
    uint32_t* AhW = (uint32_t*)Ah; uint32_t* AlW = (uint32_t*)Al;
    uint32_t* BhW = (uint32_t*)Bh; uint32_t* BlW = (uint32_t*)Bl;

    int z = blockIdx.z;
    int m0 = blockIdx.y * 128, n0 = blockIdx.x * 128;
    const float* Ab = A + (size_t)z * aStr;
    const float* Wb = W + (size_t)(z & wMask) * wStr;
    float* Cb = C + (size_t)z * cStr;

    int tid = threadIdx.x;
    int wid = tid >> 5, l = tid & 31;
    int lr = l >> 2, lc = l & 3;
    int moff = (wid & 3) * 32;        // warp m-offset (2 x m16 tiles)
    int noff = (wid >> 2) * 64;       // warp n-offset (8 x n8 tiles)

    float acc[2][8][4] = {};

    for (int k0 = 0; k0 < K; k0 += 32) {
        // ---- stage A: 128m x 32k fp32 -> bf16 hi/lo, row-major [m][k] -------
        #pragma unroll
        for (int i = 0; i < 4; i++) {
            int idx = tid + i*256;            // 0..1023
            int row = idx >> 3, k4 = (idx & 7) * 4;
            float4 a = *(const float4*)&Ab[(size_t)(m0 + row)*lda + k0 + k4];
            __nv_bfloat16 h0 = __float2bfloat16(a.x), h1 = __float2bfloat16(a.y);
            __nv_bfloat16 h2 = __float2bfloat16(a.z), h3 = __float2bfloat16(a.w);
            __nv_bfloat16 l0 = __float2bfloat16(a.x - __bfloat162float(h0));
            __nv_bfloat16 l1 = __float2bfloat16(a.y - __bfloat162float(h1));
            __nv_bfloat16 l2 = __float2bfloat16(a.z - __bfloat162float(h2));
            __nv_bfloat16 l3 = __float2bfloat16(a.w - __bfloat162float(h3));
            int wb = row*PW + k4/2;
            AhW[wb]   = pack2bf(h0, h1); AhW[wb+1] = pack2bf(h2, h3);
            AlW[wb]   = pack2bf(l0, l1); AlW[wb+1] = pack2bf(l2, l3);
        }
        // ---- stage B: 32k x 128n fp32 -> bf16 hi/lo, TRANSPOSED [n][k] ------
        #pragma unroll
        for (int i = 0; i < 4; i++) {
            int idx = tid + i*256;
            int kr = idx >> 5, n4 = (idx & 31) * 4;
            float4 w4 = *(const float4*)&Wb[(size_t)(k0 + kr)*N + n0 + n4];
            float v[4] = {w4.x, w4.y, w4.z, w4.w};
            #pragma unroll
            for (int j = 0; j < 4; j++) {
                __nv_bfloat16 h = __float2bfloat16(v[j]);
                __nv_bfloat16 lo = __float2bfloat16(v[j] - __bfloat162float(h));
                Bh[n4 + j][kr] = h;
                Bl[n4 + j][kr] = lo;
            }
        }
        __syncthreads();

        // ---- compute: 2 x k16 mma steps ------------------------------------
        #pragma unroll
        for (int kk = 0; kk < 2; kk++) {
            uint32_t ah[2][4], al[2][4];
            #pragma unroll
            for (int mt = 0; mt < 2; mt++) {
                int rb = (moff + mt*16 + lr)*PW + kk*8 + lc;
                ah[mt][0] = AhW[rb];           ah[mt][1] = AhW[rb + 8*PW];
                ah[mt][2] = AhW[rb + 4];       ah[mt][3] = AhW[rb + 8*PW + 4];
                al[mt][0] = AlW[rb];           al[mt][1] = AlW[rb + 8*PW];
                al[mt][2] = AlW[rb + 4];       al[mt][3] = AlW[rb + 8*PW + 4];
            }
            #pragma unroll
            for (int nt = 0; nt < 8; nt++) {
                int cb = (noff + nt*8 + lr)*PW + kk*8 + lc;
                uint32_t bh0 = BhW[cb], bh1 = BhW[cb + 4];
                uint32_t bl0 = BlW[cb], bl1 = BlW[cb + 4];
                #pragma unroll
                for (int mt = 0; mt < 2; mt++) {
                    mma16816(acc[mt][nt], ah[mt], bh0, bh1);
                    mma16816(acc[mt][nt], ah[mt], bl0, bl1);
                    mma16816(acc[mt][nt], al[mt], bh0, bh1);
                }
            }
        }
        __syncthreads();
    }

    // ---- epilogue: C frag m16n8: (c0,c1)@[row, col..col+1], (c2,c3)@[row+8] -
    #pragma unroll
    for (int mt = 0; mt < 2; mt++) {
        int r0 = m0 + moff + mt*16 + lr;
        #pragma unroll
        for (int nt = 0; nt < 8; nt++) {
            int c = n0 + noff + nt*8 + 2*lc;
            float* a4 = acc[mt][nt];
            if (trans) {
                Cb[(size_t)(c + 0)*Tt + r0]     = a4[0];
                Cb[(size_t)(c + 1)*Tt + r0]     = a4[1];
                Cb[(size_t)(c + 0)*Tt + r0 + 8] = a4[2];
                Cb[(size_t)(c + 1)*Tt + r0 + 8] = a4[3];
            } else {
                *(float2*)&Cb[(size_t)r0*N + c]       = make_float2(a4[0], a4[1]);
                *(float2*)&Cb[(size_t)(r0 + 8)*N + c] = make_float2(a4[2], a4[3]);
            }
        }
    }
}

// ---- dual NT GEMM (128x64 tile, 8x4/thread), single-buffer (R9 form) --------
// Sb = pb@q^T, Sd = tanh((p*Wd)@q^T)*vd
__global__ void __launch_bounds__(256, 2) gemm_bt2(
    const float* __restrict__ p, const float* __restrict__ q,
    const float* __restrict__ Wd, const float* __restrict__ vd) {
    __shared__ float As1[KB][132], As2[KB][132], Bs[KB][68];
    int b = blockIdx.z;
    int m0 = blockIdx.y * 128, n0 = blockIdx.x * 64;
    const float* pbb = g_pb + (size_t)b*Tt*Hh;
    const float* pr  = p   + (size_t)b*Tt*Hh;
    const float* qr  = q   + (size_t)b*Tt*Hh;
    int tid = threadIdx.x;
    int tx = tid & 15, ty = tid >> 4;
    uint64_t ab[8][2] = {}, ad[8][2] = {};
    for (int k0 = 0; k0 < Hh; k0 += KB) {
        #pragma unroll
        for (int i = 0; i < 2; i++) {
            int idx = tid + i*256;
            int row = idx >> 2, c4 = (idx & 3) * 4;
            float4 a1 = *(const float4*)&pbb[(size_t)(m0 + row)*Hh + k0 + c4];
            float4 a2 = *(const float4*)&pr [(size_t)(m0 + row)*Hh + k0 + c4];
            float4 wd = *(const float4*)&Wd[k0 + c4];
            As1[c4+0][row] = a1.x; As1[c4+1][row] = a1.y;
            As1[c4+2][row] = a1.z; As1[c4+3][row] = a1.w;
            As2[c4+0][row] = a2.x*wd.x; As2[c4+1][row] = a2.y*wd.y;
            As2[c4+2][row] = a2.z*wd.z; As2[c4+3][row] = a2.w*wd.w;
        }
        {
            int row = tid >> 2, c4 = (tid & 3) * 4;
            float4 bq = *(const float4*)&qr[(size_t)(n0 + row)*Hh + k0 + c4];
            Bs[c4+0][row] = bq.x; Bs[c4+1][row] = bq.y;
            Bs[c4+2][row] = bq.z; Bs[c4+3][row] = bq.w;
        }
        __syncthreads();
        #pragma unroll
        for (int k = 0; k < KB; k++) {
            float4 x0 = *(const float4*)&As1[k][ty*4];
            float4 x1 = *(const float4*)&As1[k][64 + ty*4];
            float4 y0 = *(const float4*)&As2[k][ty*4];
            float4 y1 = *(const float4*)&As2[k][64 + ty*4];
            F4U2 bb; bb.f = *(const float4*)&Bs[k][tx*4];
            float am1[8] = {x0.x, x0.y, x0.z, x0.w, x1.x, x1.y, x1.z, x1.w};
            float am2[8] = {y0.x, y0.y, y0.z, y0.w, y1.x, y1.y, y1.z, y1.w};
            #pragma unroll
            for (int mi = 0; mi < 8; mi++) {
                uint64_t aa1 = bcast2(am1[mi]);
                uint64_t aa2 = bcast2(am2[mi]);
                ffma2(ab[mi][0], aa1, bb.u[0]);
                ffma2(ab[mi][1], aa1, bb.u[1]);
                ffma2(ad[mi][0], aa2, bb.u[0]);
                ffma2(ad[mi][1], aa2, bb.u[1]);
            }
        }
        __syncthreads();
    }
    size_t base = (size_t)b*Tt*Tt;
    #pragma unroll
    for (int mi = 0; mi < 8; mi++) {
        int m = m0 + ((mi < 4) ? (ty*4 + mi) : (64 + ty*4 + mi - 4));
        #pragma unroll
        for (int np = 0; np < 2; np++) {
            int n = n0 + tx*4 + 2*np;
            float b0, b1; unpack2(ab[mi][np], b0, b1);
            float d0, d1; unpack2(ad[mi][np], d0, d1);
            *(float2*)&g_Sb[base + (size_t)m*Tt + n] = make_float2(b0, b1);
            g_Sd[base + (size_t)m*Tt + n + 0] = tanhf(d0) * vd[n + 0];
            g_Sd[base + (size_t)m*Tt + n + 1] = tanhf(d1) * vd[n + 1];
        }
    }
}

// ---------------- K3: finish scores + row softmax -> g_P ---------------------
__global__ void k_softmax(const float* __restrict__ vc, const float* __restrict__ vm) {
    int mode = blockIdx.z, b = blockIdx.y, i = blockIdx.x, j = threadIdx.x;
    size_t base = (size_t)b*Tt*Tt + (size_t)i*Tt;
    float s;
    if      (mode == 0) s = tanhf(g_whp[base + j] + g_whqT[base + j]) * vc[i];
    else if (mode == 1) s = g_Sb[base + j];
    else if (mode == 2) s = g_Sd[base + j];
    else                s = tanhf(g_qWm[b*Tt + j] - g_pWm[b*Tt + i]) * vm[j];

    float m = s;
    for (int o = 16; o; o >>= 1) m = fmaxf(m, __shfl_xor_sync(0xffffffffu, m, o));
    __shared__ float rm[8], rs[8];
    int w = j >> 5, l = j & 31;
    if (!l) rm[w] = m;
    __syncthreads();
    float mm = rm[0];
    #pragma unroll
    for (int k = 1; k < 8; k++) mm = fmaxf(mm, rm[k]);

    float e = __expf(s - mm);
    float sum = e;
    for (int o = 16; o; o >>= 1) sum += __shfl_xor_sync(0xffffffffu, sum, o);
    if (!l) rs[w] = sum;
    __syncthreads();
    float tot = 0.f;
    #pragma unroll
    for (int k = 0; k < 8; k++) tot += rs[k];

    g_P[(size_t)mode*Bb*Tt*Tt + base + j] = e / tot;
}

// ---------------- launch -----------------------------------------------------
extern "C" void kernel_launch(void* const* d_in, const int* in_sizes, int n_in,
                              void* d_out, int out_size) {
    const float* q   = (const float*)d_in[0];
    const float* p   = (const float*)d_in[1];
    const float* Wc1 = (const float*)d_in[2];
    const float* Wc2 = (const float*)d_in[3];
    const float* vc  = (const float*)d_in[4];
    const float* Wb  = (const float*)d_in[5];
    const float* Wd  = (const float*)d_in[6];
    const float* vd  = (const float*)d_in[7];
    const float* Wm  = (const float*)d_in[8];
    const float* vm  = (const float*)d_in[9];
    float* out = (float*)d_out;

    float* d_whqT; cudaGetSymbolAddress((void**)&d_whqT, g_whqT);
    float* d_whp;  cudaGetSymbolAddress((void**)&d_whp,  g_whp);
    float* d_pb;   cudaGetSymbolAddress((void**)&d_pb,   g_pb);
    float* d_P;    cudaGetSymbolAddress((void**)&d_P,    g_P);

    k_vec<<<dim3(Tt, Bb), 256>>>(q, p, Wm);
    // whqT[b] = (q[b] @ Wc1) stored transposed
    gemm128t<<<dim3(2, 2, Bb), 256>>>(q, (size_t)Tt*Hh, Hh,
                                      Wc1, 0, 0, Tt,
                                      d_whqT, (size_t)Tt*Tt, Hh, 1);
    // whp[b] = p[b] @ Wc2
    gemm128t<<<dim3(2, 2, Bb), 256>>>(p, (size_t)Tt*Hh, Hh,
                                      Wc2, 0, 0, Tt,
                                      d_whp, (size_t)Tt*Tt, Hh, 0);
    // pb[b] = p[b] @ Wb
    gemm128t<<<dim3(6, 2, Bb), 256>>>(p, (size_t)Tt*Hh, Hh,
                                      Wb, 0, 0, Hh,
                                      d_pb, (size_t)Tt*Hh, Hh, 0);
    // Sb, Sd
    gemm_bt2<<<dim3(4, 2, Bb), 256>>>(p, q, Wd, vd);
    // 4x softmax
    k_softmax<<<dim3(Tt, Bb, 4), 256>>>(vc, vm);
    // out[z] = P[z] @ q[z&63], z = type*64 + b
    gemm128t<<<dim3(6, 2, 4*Bb), 256>>>(d_P, (size_t)Tt*Tt, Tt,
                                        q, (size_t)Tt*Hh, 63, Hh,
                                        out, (size_t)Tt*Hh, Tt, 0);
}

// round 14
// speedup vs baseline: 1.7758x; 1.7758x over previous
#include <cuda_runtime.h>
#include <cuda_bf16.h>
#include <cstdint>
#include <math.h>

#define Bb 64
#define Tt 256
#define Hh 768
#define KB 16

// ---------------- packed f32x2 helpers ---------------------------------------
__device__ __forceinline__ void ffma2(uint64_t& d, uint64_t a, uint64_t b) {
    asm("fma.rn.f32x2 %0, %1, %2, %0;" : "+l"(d) : "l"(a), "l"(b));
}
__device__ __forceinline__ uint64_t bcast2(float x) {
    uint64_t r;
    asm("mov.b64 %0, {%1, %1};" : "=l"(r) : "f"(x));
    return r;
}
__device__ __forceinline__ void unpack2(uint64_t v, float& lo, float& hi) {
    asm("mov.b64 {%0, %1}, %2;" : "=f"(lo), "=f"(hi) : "l"(v));
}
union F4U2 { float4 f; uint64_t u[2]; };

// ---------------- bf16 mma / ldmatrix helpers --------------------------------
__device__ __forceinline__ uint32_t pack2bf(__nv_bfloat16 f0, __nv_bfloat16 f1) {
    __nv_bfloat162 h; h.x = f0; h.y = f1;
    return *reinterpret_cast<uint32_t*>(&h);
}
__device__ __forceinline__ void mma16816(float* c, const uint32_t* a, uint32_t b0, uint32_t b1) {
    asm("mma.sync.aligned.m16n8k16.row.col.f32.bf16.bf16.f32 "
        "{%0,%1,%2,%3}, {%4,%5,%6,%7}, {%8,%9}, {%0,%1,%2,%3};"
        : "+f"(c[0]), "+f"(c[1]), "+f"(c[2]), "+f"(c[3])
        : "r"(a[0]), "r"(a[1]), "r"(a[2]), "r"(a[3]), "r"(b0), "r"(b1));
}
__device__ __forceinline__ void ldsm4(uint32_t* r, uint32_t a) {
    asm volatile("ldmatrix.sync.aligned.m8n8.x4.shared.b16 {%0,%1,%2,%3}, [%4];"
        : "=r"(r[0]), "=r"(r[1]), "=r"(r[2]), "=r"(r[3]) : "r"(a));
}
__device__ __forceinline__ void ldsm4t(uint32_t* r, uint32_t a) {
    asm volatile("ldmatrix.sync.aligned.m8n8.x4.trans.shared.b16 {%0,%1,%2,%3}, [%4];"
        : "=r"(r[0]), "=r"(r[1]), "=r"(r[2]), "=r"(r[3]) : "r"(a));
}
__device__ __forceinline__ uint32_t smem_u32(const void* p) {
    return (uint32_t)__cvta_generic_to_shared(p);
}

// ---------------- scratch (static device globals; no allocation) -------------
__device__ float g_whqT[(size_t)Bb*Tt*Tt];
__device__ float g_whp [(size_t)Bb*Tt*Tt];
__device__ float g_pb  [(size_t)Bb*Tt*Hh];
__device__ float g_Sb  [(size_t)Bb*Tt*Tt];
__device__ float g_Sd  [(size_t)Bb*Tt*Tt];
__device__ float g_qWm[Bb*Tt];
__device__ float g_pWm[Bb*Tt];
// bf16 hi/lo persistent operands
__device__ __nv_bfloat16 g_qh[(size_t)Bb*Tt*Hh], g_ql[(size_t)Bb*Tt*Hh];
__device__ __nv_bfloat16 g_ph[(size_t)Bb*Tt*Hh], g_pl[(size_t)Bb*Tt*Hh];
__device__ __nv_bfloat16 g_W1h[Hh*Tt], g_W1l[Hh*Tt];
__device__ __nv_bfloat16 g_W2h[Hh*Tt], g_W2l[Hh*Tt];
__device__ __nv_bfloat16 g_Wbh[Hh*Hh], g_Wbl[Hh*Hh];
__device__ __nv_bfloat16 g_Ph[(size_t)4*Bb*Tt*Tt], g_Pl[(size_t)4*Bb*Tt*Tt];

// ---------------- K-1: fp32 -> bf16 hi/lo convert (8 elems/thread) -----------
__global__ void k_cvt(const float* __restrict__ in, __nv_bfloat16* __restrict__ hi,
                      __nv_bfloat16* __restrict__ lo, int n8) {
    int i = blockIdx.x*256 + threadIdx.x;
    if (i >= n8) return;
    float4 v0 = ((const float4*)in)[i*2];
    float4 v1 = ((const float4*)in)[i*2 + 1];
    float v[8] = {v0.x, v0.y, v0.z, v0.w, v1.x, v1.y, v1.z, v1.w};
    uint32_t hp[4], lp[4];
    #pragma unroll
    for (int j = 0; j < 4; j++) {
        __nv_bfloat16 h0 = __float2bfloat16(v[2*j]);
        __nv_bfloat16 h1 = __float2bfloat16(v[2*j+1]);
        __nv_bfloat16 l0 = __float2bfloat16(v[2*j]   - __bfloat162float(h0));
        __nv_bfloat16 l1 = __float2bfloat16(v[2*j+1] - __bfloat162float(h1));
        hp[j] = pack2bf(h0, h1);
        lp[j] = pack2bf(l0, l1);
    }
    ((uint4*)hi)[i] = make_uint4(hp[0], hp[1], hp[2], hp[3]);
    ((uint4*)lo)[i] = make_uint4(lp[0], lp[1], lp[2], lp[3]);
}

// ---------------- K0: qWm[b,t] = q[b,t,:]@Wm ; pWm likewise ------------------
__global__ void k_vec(const float* __restrict__ q, const float* __restrict__ p,
                      const float* __restrict__ Wm) {
    int b = blockIdx.y, t = blockIdx.x, tid = threadIdx.x;
    const float* qr = q + ((size_t)b*Tt + t)*Hh;
    const float* pr = p + ((size_t)b*Tt + t)*Hh;
    float sq = 0.f, sp = 0.f;
    for (int h = tid; h < Hh; h += 256) {
        float w = Wm[h];
        sq += qr[h]*w; sp += pr[h]*w;
    }
    for (int o = 16; o; o >>= 1) {
        sq += __shfl_down_sync(0xffffffffu, sq, o);
        sp += __shfl_down_sync(0xffffffffu, sp, o);
    }
    __shared__ float ssq[8], ssp[8];
    int w = tid >> 5, l = tid & 31;
    if (!l) { ssq[w] = sq; ssp[w] = sp; }
    __syncthreads();
    if (tid == 0) {
        float a = 0.f, c = 0.f;
        for (int i = 0; i < 8; i++) { a += ssq[i]; c += ssp[i]; }
        g_qWm[b*Tt + t] = a;
        g_pWm[b*Tt + t] = c;
    }
}

// ======== tensor-core 128x128 batched GEMM (pre-split bf16, ldmatrix) ========
// C[z] = A[z](MxK) @ W[z](KxN); A bf16 hi/lo row-major pitch lda;
// W bf16 hi/lo row-major pitch N. A += z*aStr, W += (z&wMask)*wStr, C += z*cStr.
// trans!=0 -> C[n*Tt + m]. Split: D = Ah*Bh + Ah*Bl + Al*Bh (fp32 accum).
__global__ void __launch_bounds__(256, 2) gemm128t(
    const __nv_bfloat16* __restrict__ Ahg, const __nv_bfloat16* __restrict__ Alg,
    size_t aStr, int lda,
    const __nv_bfloat16* __restrict__ Whg, const __nv_bfloat16* __restrict__ Wlg,
    size_t wStr, int wMask, int N,
    float* __restrict__ C, size_t cStr, int K, int trans) {
    __shared__ __nv_bfloat16 Ah[128][40], Al[128][40];   // [m][k], pad 40
    __shared__ __nv_bfloat16 Bh[32][136], Bl[32][136];   // [k][n], pad 136

    int z = blockIdx.z;
    int m0 = blockIdx.y * 128, n0 = blockIdx.x * 128;
    const __nv_bfloat16* Abh = Ahg + (size_t)z * aStr;
    const __nv_bfloat16* Abl = Alg + (size_t)z * aStr;
    const __nv_bfloat16* Wbh = Whg + (size_t)(z & wMask) * wStr;
    const __nv_bfloat16* Wbl = Wlg + (size_t)(z & wMask) * wStr;
    float* Cb = C + (size_t)z * cStr;

    int tid = threadIdx.x;
    int wid = tid >> 5, l = tid & 31;
    int moff = (wid & 3) * 32;        // 2 x m16 tiles
    int noff = (wid >> 2) * 64;       // 8 x n8 tiles

    uint32_t ahB = smem_u32(Ah), alB = smem_u32(Al);
    uint32_t bhB = smem_u32(Bh), blB = smem_u32(Bl);

    // fragment smem addresses (constant across k-loop)
    uint32_t aOff[2], bOff[4];
    #pragma unroll
    for (int mt = 0; mt < 2; mt++)
        aOff[mt] = ((moff + mt*16 + (l & 15))*40 + (l >> 4)*8) * 2;
    #pragma unroll
    for (int ng = 0; ng < 4; ng++) {
        int kB = (l & 7) + ((l >> 3) & 1)*8;
        int nB = noff + ng*16 + (l >> 4)*8;
        bOff[ng] = (kB*136 + nB) * 2;
    }

    float acc[2][8][4] = {};

    for (int k0 = 0; k0 < K; k0 += 32) {
        // stage A: 128 x 32 bf16 (hi & lo), uint4 copies (2 x 256 threads)
        #pragma unroll
        for (int i = 0; i < 2; i++) {
            int idx = tid + i*256;            // 0..511
            int row = idx >> 2, seg = idx & 3;
            size_t g = (size_t)(m0 + row)*lda + k0 + seg*8;
            *(uint4*)&Ah[row][seg*8] = *(const uint4*)&Abh[g];
            *(uint4*)&Al[row][seg*8] = *(const uint4*)&Abl[g];
        }
        // stage B: 32 x 128 bf16 (hi & lo) — FULL coverage: 2 x 256 threads
        #pragma unroll
        for (int i = 0; i < 2; i++) {
            int idx = tid + i*256;            // 0..511
            int kr = idx >> 4, seg = idx & 15;   // 32 rows x 16 segs x 8 = 128 cols
            size_t g = (size_t)(k0 + kr)*N + n0 + seg*8;
            *(uint4*)&Bh[kr][seg*8] = *(const uint4*)&Wbh[g];
            *(uint4*)&Bl[kr][seg*8] = *(const uint4*)&Wbl[g];
        }
        __syncthreads();

        #pragma unroll
        for (int kk = 0; kk < 2; kk++) {
            uint32_t ah[2][4], al[2][4];
            #pragma unroll
            for (int mt = 0; mt < 2; mt++) {
                uint32_t ao = aOff[mt] + kk*32;     // +16 bf16 in k
                ldsm4(ah[mt], ahB + ao);
                ldsm4(al[mt], alB + ao);
            }
            #pragma unroll
            for (int ng = 0; ng < 4; ng++) {
                uint32_t bo = bOff[ng] + kk*16*136*2;
                uint32_t bh[4], bl[4];
                ldsm4t(bh, bhB + bo);
                ldsm4t(bl, blB + bo);
                #pragma unroll
                for (int mt = 0; mt < 2; mt++) {
                    mma16816(acc[mt][2*ng],   ah[mt], bh[0], bh[1]);
                    mma16816(acc[mt][2*ng],   ah[mt], bl[0], bl[1]);
                    mma16816(acc[mt][2*ng],   al[mt], bh[0], bh[1]);
                    mma16816(acc[mt][2*ng+1], ah[mt], bh[2], bh[3]);
                    mma16816(acc[mt][2*ng+1], ah[mt], bl[2], bl[3]);
                    mma16816(acc[mt][2*ng+1], al[mt], bh[2], bh[3]);
                }
            }
        }
        __syncthreads();
    }

    int lr = l >> 2, lc = l & 3;
    #pragma unroll
    for (int mt = 0; mt < 2; mt++) {
        int r0 = m0 + moff + mt*16 + lr;
        #pragma unroll
        for (int nt = 0; nt < 8; nt++) {
            int c = n0 + noff + nt*8 + 2*lc;
            float* a4 = acc[mt][nt];
            if (trans) {
                Cb[(size_t)(c + 0)*Tt + r0]     = a4[0];
                Cb[(size_t)(c + 1)*Tt + r0]     = a4[1];
                Cb[(size_t)(c + 0)*Tt + r0 + 8] = a4[2];
                Cb[(size_t)(c + 1)*Tt + r0 + 8] = a4[3];
            } else {
                *(float2*)&Cb[(size_t)r0*N + c]       = make_float2(a4[0], a4[1]);
                *(float2*)&Cb[(size_t)(r0 + 8)*N + c] = make_float2(a4[2], a4[3]);
            }
        }
    }
}

// ---- dual NT GEMM (128x64 tile, 8x4/thread), single-buffer ------------------
__global__ void __launch_bounds__(256, 2) gemm_bt2(
    const float* __restrict__ p, const float* __restrict__ q,
    const float* __restrict__ Wd, const float* __restrict__ vd) {
    __shared__ float As1[KB][132], As2[KB][132], Bs[KB][68];
    int b = blockIdx.z;
    int m0 = blockIdx.y * 128, n0 = blockIdx.x * 64;
    const float* pbb = g_pb + (size_t)b*Tt*Hh;
    const float* pr  = p   + (size_t)b*Tt*Hh;
    const float* qr  = q   + (size_t)b*Tt*Hh;
    int tid = threadIdx.x;
    int tx = tid & 15, ty = tid >> 4;
    uint64_t ab[8][2] = {}, ad[8][2] = {};
    for (int k0 = 0; k0 < Hh; k0 += KB) {
        #pragma unroll
        for (int i = 0; i < 2; i++) {
            int idx = tid + i*256;
            int row = idx >> 2, c4 = (idx & 3) * 4;
            float4 a1 = *(const float4*)&pbb[(size_t)(m0 + row)*Hh + k0 + c4];
            float4 a2 = *(const float4*)&pr [(size_t)(m0 + row)*Hh + k0 + c4];
            float4 wd = *(const float4*)&Wd[k0 + c4];
            As1[c4+0][row] = a1.x; As1[c4+1][row] = a1.y;
            As1[c4+2][row] = a1.z; As1[c4+3][row] = a1.w;
            As2[c4+0][row] = a2.x*wd.x; As2[c4+1][row] = a2.y*wd.y;
            As2[c4+2][row] = a2.z*wd.z; As2[c4+3][row] = a2.w*wd.w;
        }
        {
            int row = tid >> 2, c4 = (tid & 3) * 4;
            float4 bq = *(const float4*)&qr[(size_t)(n0 + row)*Hh + k0 + c4];
            Bs[c4+0][row] = bq.x; Bs[c4+1][row] = bq.y;
            Bs[c4+2][row] = bq.z; Bs[c4+3][row] = bq.w;
        }
        __syncthreads();
        #pragma unroll
        for (int k = 0; k < KB; k++) {
            float4 x0 = *(const float4*)&As1[k][ty*4];
            float4 x1 = *(const float4*)&As1[k][64 + ty*4];
            float4 y0 = *(const float4*)&As2[k][ty*4];
            float4 y1 = *(const float4*)&As2[k][64 + ty*4];
            F4U2 bb; bb.f = *(const float4*)&Bs[k][tx*4];
            float am1[8] = {x0.x, x0.y, x0.z, x0.w, x1.x, x1.y, x1.z, x1.w};
            float am2[8] = {y0.x, y0.y, y0.z, y0.w, y1.x, y1.y, y1.z, y1.w};
            #pragma unroll
            for (int mi = 0; mi < 8; mi++) {
                uint64_t aa1 = bcast2(am1[mi]);
                uint64_t aa2 = bcast2(am2[mi]);
                ffma2(ab[mi][0], aa1, bb.u[0]);
                ffma2(ab[mi][1], aa1, bb.u[1]);
                ffma2(ad[mi][0], aa2, bb.u[0]);
                ffma2(ad[mi][1], aa2, bb.u[1]);
            }
        }
        __syncthreads();
    }
    size_t base = (size_t)b*Tt*Tt;
    #pragma unroll
    for (int mi = 0; mi < 8; mi++) {
        int m = m0 + ((mi < 4) ? (ty*4 + mi) : (64 + ty*4 + mi - 4));
        #pragma unroll
        for (int np = 0; np < 2; np++) {
            int n = n0 + tx*4 + 2*np;
            float b0, b1; unpack2(ab[mi][np], b0, b1);
            float d0, d1; unpack2(ad[mi][np], d0, d1);
            *(float2*)&g_Sb[base + (size_t)m*Tt + n] = make_float2(b0, b1);
            g_Sd[base + (size_t)m*Tt + n + 0] = tanhf(d0) * vd[n + 0];
            g_Sd[base + (size_t)m*Tt + n + 1] = tanhf(d1) * vd[n + 1];
        }
    }
}

// ---------------- K3: finish scores + row softmax -> bf16 hi/lo P ------------
__global__ void k_softmax(const float* __restrict__ vc, const float* __restrict__ vm) {
    int mode = blockIdx.z, b = blockIdx.y, i = blockIdx.x, j = threadIdx.x;
    size_t base = (size_t)b*Tt*Tt + (size_t)i*Tt;
    float s;
    if      (mode == 0) s = tanhf(g_whp[base + j] + g_whqT[base + j]) * vc[i];
    else if (mode == 1) s = g_Sb[base + j];
    else if (mode == 2) s = g_Sd[base + j];
    else                s = tanhf(g_qWm[b*Tt + j] - g_pWm[b*Tt + i]) * vm[j];

    float m = s;
    for (int o = 16; o; o >>= 1) m = fmaxf(m, __shfl_xor_sync(0xffffffffu, m, o));
    __shared__ float rm[8], rs[8];
    int w = j >> 5, l = j & 31;
    if (!l) rm[w] = m;
    __syncthreads();
    float mm = rm[0];
    #pragma unroll
    for (int k = 1; k < 8; k++) mm = fmaxf(mm, rm[k]);

    float e = __expf(s - mm);
    float sum = e;
    for (int o = 16; o; o >>= 1) sum += __shfl_xor_sync(0xffffffffu, sum, o);
    if (!l) rs[w] = sum;
    __syncthreads();
    float tot = 0.f;
    #pragma unroll
    for (int k = 0; k < 8; k++) tot += rs[k];

    float prob = e / tot;
    size_t idx = (size_t)mode*Bb*Tt*Tt + base + j;
    __nv_bfloat16 h = __float2bfloat16(prob);
    g_Ph[idx] = h;
    g_Pl[idx] = __float2bfloat16(prob - __bfloat162float(h));
}

// ---------------- launch -----------------------------------------------------
extern "C" void kernel_launch(void* const* d_in, const int* in_sizes, int n_in,
                              void* d_out, int out_size) {
    const float* q   = (const float*)d_in[0];
    const float* p   = (const float*)d_in[1];
    const float* Wc1 = (const float*)d_in[2];
    const float* Wc2 = (const float*)d_in[3];
    const float* vc  = (const float*)d_in[4];
    const float* Wb  = (const float*)d_in[5];
    const float* Wd  = (const float*)d_in[6];
    const float* vd  = (const float*)d_in[7];
    const float* Wm  = (const float*)d_in[8];
    const float* vm  = (const float*)d_in[9];
    float* out = (float*)d_out;

    float* d_whqT; cudaGetSymbolAddress((void**)&d_whqT, g_whqT);
    float* d_whp;  cudaGetSymbolAddress((void**)&d_whp,  g_whp);
    float* d_pb;   cudaGetSymbolAddress((void**)&d_pb,   g_pb);
    __nv_bfloat16 *d_qh, *d_ql, *d_ph, *d_pl, *d_W1h, *d_W1l, *d_W2h, *d_W2l;
    __nv_bfloat16 *d_Wbh, *d_Wbl, *d_Ph, *d_Pl;
    cudaGetSymbolAddress((void**)&d_qh, g_qh);   cudaGetSymbolAddress((void**)&d_ql, g_ql);
    cudaGetSymbolAddress((void**)&d_ph, g_ph);   cudaGetSymbolAddress((void**)&d_pl, g_pl);
    cudaGetSymbolAddress((void**)&d_W1h, g_W1h); cudaGetSymbolAddress((void**)&d_W1l, g_W1l);
    cudaGetSymbolAddress((void**)&d_W2h, g_W2h); cudaGetSymbolAddress((void**)&d_W2l, g_W2l);
    cudaGetSymbolAddress((void**)&d_Wbh, g_Wbh); cudaGetSymbolAddress((void**)&d_Wbl, g_Wbl);
    cudaGetSymbolAddress((void**)&d_Ph, g_Ph);   cudaGetSymbolAddress((void**)&d_Pl, g_Pl);

    const int nQP8 = Bb*Tt*Hh/8;        // 1572864
    k_cvt<<<(nQP8 + 255)/256, 256>>>(q, d_qh, d_ql, nQP8);
    k_cvt<<<(nQP8 + 255)/256, 256>>>(p, d_ph, d_pl, nQP8);
    k_cvt<<<(Hh*Tt/8 + 255)/256, 256>>>(Wc1, d_W1h, d_W1l, Hh*Tt/8);
    k_cvt<<<(Hh*Tt/8 + 255)/256, 256>>>(Wc2, d_W2h, d_W2l, Hh*Tt/8);
    k_cvt<<<(Hh*Hh/8 + 255)/256, 256>>>(Wb, d_Wbh, d_Wbl, Hh*Hh/8);

    k_vec<<<dim3(Tt, Bb), 256>>>(q, p, Wm);
    // whqT[b] = (q[b] @ Wc1) stored transposed
    gemm128t<<<dim3(2, 2, Bb), 256>>>(d_qh, d_ql, (size_t)Tt*Hh, Hh,
                                      d_W1h, d_W1l, 0, 0, Tt,
                                      d_whqT, (size_t)Tt*Tt, Hh, 1);
    // whp[b] = p[b] @ Wc2
    gemm128t<<<dim3(2, 2, Bb), 256>>>(d_ph, d_pl, (size_t)Tt*Hh, Hh,
                                      d_W2h, d_W2l, 0, 0, Tt,
                                      d_whp, (size_t)Tt*Tt, Hh, 0);
    // pb[b] = p[b] @ Wb
    gemm128t<<<dim3(6, 2, Bb), 256>>>(d_ph, d_pl, (size_t)Tt*Hh, Hh,
                                      d_Wbh, d_Wbl, 0, 0, Hh,
                                      d_pb, (size_t)Tt*Hh, Hh, 0);
    // Sb, Sd
    gemm_bt2<<<dim3(4, 2, Bb), 256>>>(p, q, Wd, vd);
    // 4x softmax -> Ph/Pl
    k_softmax<<<dim3(Tt, Bb, 4), 256>>>(vc, vm);
    // out[z] = P[z] @ q[z&63]
    gemm128t<<<dim3(6, 2, 4*Bb), 256>>>(d_Ph, d_Pl, (size_t)Tt*Tt, Tt,
                                        d_qh, d_ql, (size_t)Tt*Hh, 63, Hh,
                                        out, (size_t)Tt*Hh, Tt, 0);
}

// round 17
// speedup vs baseline: 2.1593x; 1.2160x over previous
#include <cuda_runtime.h>
#include <cuda_bf16.h>
#include <cstdint>
#include <math.h>

#define Bb 64
#define Tt 256
#define Hh 768

// ---------------- bf16 mma / ldmatrix helpers --------------------------------
__device__ __forceinline__ uint32_t pack2bf(__nv_bfloat16 f0, __nv_bfloat16 f1) {
    __nv_bfloat162 h; h.x = f0; h.y = f1;
    return *reinterpret_cast<uint32_t*>(&h);
}
__device__ __forceinline__ void mma16816(float* c, const uint32_t* a, uint32_t b0, uint32_t b1) {
    asm("mma.sync.aligned.m16n8k16.row.col.f32.bf16.bf16.f32 "
        "{%0,%1,%2,%3}, {%4,%5,%6,%7}, {%8,%9}, {%0,%1,%2,%3};"
        : "+f"(c[0]), "+f"(c[1]), "+f"(c[2]), "+f"(c[3])
        : "r"(a[0]), "r"(a[1]), "r"(a[2]), "r"(a[3]), "r"(b0), "r"(b1));
}
__device__ __forceinline__ void ldsm4(uint32_t* r, uint32_t a) {
    asm volatile("ldmatrix.sync.aligned.m8n8.x4.shared.b16 {%0,%1,%2,%3}, [%4];"
        : "=r"(r[0]), "=r"(r[1]), "=r"(r[2]), "=r"(r[3]) : "r"(a));
}
__device__ __forceinline__ void ldsm4t(uint32_t* r, uint32_t a) {
    asm volatile("ldmatrix.sync.aligned.m8n8.x4.trans.shared.b16 {%0,%1,%2,%3}, [%4];"
        : "=r"(r[0]), "=r"(r[1]), "=r"(r[2]), "=r"(r[3]) : "r"(a));
}
__device__ __forceinline__ uint32_t smem_u32(const void* p) {
    return (uint32_t)__cvta_generic_to_shared(p);
}

// ---------------- scratch (static device globals; no allocation) -------------
__device__ float g_whqT[(size_t)Bb*Tt*Tt];
__device__ float g_whp [(size_t)Bb*Tt*Tt];
__device__ float g_Sb  [(size_t)Bb*Tt*Tt];
__device__ float g_Sd  [(size_t)Bb*Tt*Tt];
__device__ float g_qWm[Bb*Tt];
__device__ float g_pWm[Bb*Tt];
// bf16 hi/lo persistent operands
__device__ __nv_bfloat16 g_qh[(size_t)Bb*Tt*Hh], g_ql[(size_t)Bb*Tt*Hh];
__device__ __nv_bfloat16 g_ph[(size_t)Bb*Tt*Hh], g_pl[(size_t)Bb*Tt*Hh];
__device__ __nv_bfloat16 g_pdh[(size_t)Bb*Tt*Hh], g_pdl[(size_t)Bb*Tt*Hh];  // p*Wd
__device__ __nv_bfloat16 g_pbh[(size_t)Bb*Tt*Hh], g_pbl[(size_t)Bb*Tt*Hh];  // p@Wb
__device__ __nv_bfloat16 g_W1h[Hh*Tt], g_W1l[Hh*Tt];
__device__ __nv_bfloat16 g_W2h[Hh*Tt], g_W2l[Hh*Tt];
__device__ __nv_bfloat16 g_Wbh[Hh*Hh], g_Wbl[Hh*Hh];
__device__ __nv_bfloat16 g_Ph[(size_t)4*Bb*Tt*Tt], g_Pl[(size_t)4*Bb*Tt*Tt];

// ---------------- K-1: fp32 -> bf16 hi/lo convert (8 elems/thread) -----------
__global__ void k_cvt(const float* __restrict__ in, __nv_bfloat16* __restrict__ hi,
                      __nv_bfloat16* __restrict__ lo, int n8) {
    int i = blockIdx.x*256 + threadIdx.x;
    if (i >= n8) return;
    float4 v0 = ((const float4*)in)[i*2];
    float4 v1 = ((const float4*)in)[i*2 + 1];
    float v[8] = {v0.x, v0.y, v0.z, v0.w, v1.x, v1.y, v1.z, v1.w};
    uint32_t hp[4], lp[4];
    #pragma unroll
    for (int j = 0; j < 4; j++) {
        __nv_bfloat16 h0 = __float2bfloat16(v[2*j]);
        __nv_bfloat16 h1 = __float2bfloat16(v[2*j+1]);
        __nv_bfloat16 l0 = __float2bfloat16(v[2*j]   - __bfloat162float(h0));
        __nv_bfloat16 l1 = __float2bfloat16(v[2*j+1] - __bfloat162float(h1));
        hp[j] = pack2bf(h0, h1);
        lp[j] = pack2bf(l0, l1);
    }
    ((uint4*)hi)[i] = make_uint4(hp[0], hp[1], hp[2], hp[3]);
    ((uint4*)lo)[i] = make_uint4(lp[0], lp[1], lp[2], lp[3]);
}

// ---- K-1b: pd = p * Wd[h] (broadcast over h), -> bf16 hi/lo -----------------
__global__ void k_cvt_wd(const float* __restrict__ p, const float* __restrict__ Wd,
                         __nv_bfloat16* __restrict__ hi, __nv_bfloat16* __restrict__ lo,
                         int n8) {
    int i = blockIdx.x*256 + threadIdx.x;
    if (i >= n8) return;
    int hbase = (i*8) % Hh;
    float4 v0 = ((const float4*)p)[i*2];
    float4 v1 = ((const float4*)p)[i*2 + 1];
    float4 w0 = *(const float4*)&Wd[hbase];
    float4 w1 = *(const float4*)&Wd[hbase + 4];
    float v[8] = {v0.x*w0.x, v0.y*w0.y, v0.z*w0.z, v0.w*w0.w,
                  v1.x*w1.x, v1.y*w1.y, v1.z*w1.z, v1.w*w1.w};
    uint32_t hp[4], lp[4];
    #pragma unroll
    for (int j = 0; j < 4; j++) {
        __nv_bfloat16 h0 = __float2bfloat16(v[2*j]);
        __nv_bfloat16 h1 = __float2bfloat16(v[2*j+1]);
        __nv_bfloat16 l0 = __float2bfloat16(v[2*j]   - __bfloat162float(h0));
        __nv_bfloat16 l1 = __float2bfloat16(v[2*j+1] - __bfloat162float(h1));
        hp[j] = pack2bf(h0, h1);
        lp[j] = pack2bf(l0, l1);
    }
    ((uint4*)hi)[i] = make_uint4(hp[0], hp[1], hp[2], hp[3]);
    ((uint4*)lo)[i] = make_uint4(lp[0], lp[1], lp[2], lp[3]);
}

// ---------------- K0: qWm[b,t] = q[b,t,:]@Wm ; pWm likewise ------------------
__global__ void k_vec(const float* __restrict__ q, const float* __restrict__ p,
                      const float* __restrict__ Wm) {
    int b = blockIdx.y, t = blockIdx.x, tid = threadIdx.x;
    const float* qr = q + ((size_t)b*Tt + t)*Hh;
    const float* pr = p + ((size_t)b*Tt + t)*Hh;
    float sq = 0.f, sp = 0.f;
    for (int h = tid; h < Hh; h += 256) {
        float w = Wm[h];
        sq += qr[h]*w; sp += pr[h]*w;
    }
    for (int o = 16; o; o >>= 1) {
        sq += __shfl_down_sync(0xffffffffu, sq, o);
        sp += __shfl_down_sync(0xffffffffu, sp, o);
    }
    __shared__ float ssq[8], ssp[8];
    int w = tid >> 5, l = tid & 31;
    if (!l) { ssq[w] = sq; ssp[w] = sp; }
    __syncthreads();
    if (tid == 0) {
        float a = 0.f, c = 0.f;
        for (int i = 0; i < 8; i++) { a += ssq[i]; c += ssp[i]; }
        g_qWm[b*Tt + t] = a;
        g_pWm[b*Tt + t] = c;
    }
}

// ======== tensor-core 128x128 batched GEMM (pre-split bf16, ldmatrix) ========
// C[z] = A[z](MxK) @ W[z](KxN). trans!=0 -> C[n*Tt+m].
// If Chg != nullptr, write bf16 hi/lo split to Chg/Clg (row-major) instead of C.
__global__ void __launch_bounds__(256, 2) gemm128t(
    const __nv_bfloat16* __restrict__ Ahg, const __nv_bfloat16* __restrict__ Alg,
    size_t aStr, int lda,
    const __nv_bfloat16* __restrict__ Whg, const __nv_bfloat16* __restrict__ Wlg,
    size_t wStr, int wMask, int N,
    float* __restrict__ C, __nv_bfloat16* __restrict__ Chg,
    __nv_bfloat16* __restrict__ Clg, size_t cStr, int K, int trans) {
    __shared__ __nv_bfloat16 Ah[128][40], Al[128][40];   // [m][k]
    __shared__ __nv_bfloat16 Bh[32][136], Bl[32][136];   // [k][n]

    int z = blockIdx.z;
    int m0 = blockIdx.y * 128, n0 = blockIdx.x * 128;
    const __nv_bfloat16* Abh = Ahg + (size_t)z * aStr;
    const __nv_bfloat16* Abl = Alg + (size_t)z * aStr;
    const __nv_bfloat16* Wbh = Whg + (size_t)(z & wMask) * wStr;
    const __nv_bfloat16* Wbl = Wlg + (size_t)(z & wMask) * wStr;

    int tid = threadIdx.x;
    int wid = tid >> 5, l = tid & 31;
    int moff = (wid & 3) * 32;        // 2 x m16 tiles
    int noff = (wid >> 2) * 64;       // 8 x n8 tiles

    uint32_t ahB = smem_u32(Ah), alB = smem_u32(Al);
    uint32_t bhB = smem_u32(Bh), blB = smem_u32(Bl);

    uint32_t aOff[2], bOff[4];
    #pragma unroll
    for (int mt = 0; mt < 2; mt++)
        aOff[mt] = ((moff + mt*16 + (l & 15))*40 + (l >> 4)*8) * 2;
    #pragma unroll
    for (int ng = 0; ng < 4; ng++) {
        int kB = (l & 7) + ((l >> 3) & 1)*8;
        int nB = noff + ng*16 + (l >> 4)*8;
        bOff[ng] = (kB*136 + nB) * 2;
    }

    float acc[2][8][4] = {};

    for (int k0 = 0; k0 < K; k0 += 32) {
        #pragma unroll
        for (int i = 0; i < 2; i++) {
            int idx = tid + i*256;
            int row = idx >> 2, seg = idx & 3;
            size_t g = (size_t)(m0 + row)*lda + k0 + seg*8;
            *(uint4*)&Ah[row][seg*8] = *(const uint4*)&Abh[g];
            *(uint4*)&Al[row][seg*8] = *(const uint4*)&Abl[g];
        }
        #pragma unroll
        for (int i = 0; i < 2; i++) {
            int idx = tid + i*256;
            int kr = idx >> 4, seg = idx & 15;
            size_t g = (size_t)(k0 + kr)*N + n0 + seg*8;
            *(uint4*)&Bh[kr][seg*8] = *(const uint4*)&Wbh[g];
            *(uint4*)&Bl[kr][seg*8] = *(const uint4*)&Wbl[g];
        }
        __syncthreads();

        #pragma unroll
        for (int kk = 0; kk < 2; kk++) {
            uint32_t ah[2][4], al[2][4];
            #pragma unroll
            for (int mt = 0; mt < 2; mt++) {
                uint32_t ao = aOff[mt] + kk*32;
                ldsm4(ah[mt], ahB + ao);
                ldsm4(al[mt], alB + ao);
            }
            #pragma unroll
            for (int ng = 0; ng < 4; ng++) {
                uint32_t bo = bOff[ng] + kk*16*136*2;
                uint32_t bh[4], bl[4];
                ldsm4t(bh, bhB + bo);
                ldsm4t(bl, blB + bo);
                #pragma unroll
                for (int mt = 0; mt < 2; mt++) {
                    mma16816(acc[mt][2*ng],   ah[mt], bh[0], bh[1]);
                    mma16816(acc[mt][2*ng],   ah[mt], bl[0], bl[1]);
                    mma16816(acc[mt][2*ng],   al[mt], bh[0], bh[1]);
                    mma16816(acc[mt][2*ng+1], ah[mt], bh[2], bh[3]);
                    mma16816(acc[mt][2*ng+1], ah[mt], bl[2], bl[3]);
                    mma16816(acc[mt][2*ng+1], al[mt], bh[2], bh[3]);
                }
            }
        }
        __syncthreads();
    }

    int lr = l >> 2, lc = l & 3;
    #pragma unroll
    for (int mt = 0; mt < 2; mt++) {
        int r0 = m0 + moff + mt*16 + lr;
        #pragma unroll
        for (int nt = 0; nt < 8; nt++) {
            int c = n0 + noff + nt*8 + 2*lc;
            float* a4 = acc[mt][nt];
            if (Chg) {
                #pragma unroll
                for (int rr = 0; rr < 2; rr++) {
                    size_t o = (size_t)z*cStr + (size_t)(r0 + rr*8)*N + c;
                    __nv_bfloat16 h0 = __float2bfloat16(a4[2*rr]);
                    __nv_bfloat16 h1 = __float2bfloat16(a4[2*rr+1]);
                    __nv_bfloat16 l0 = __float2bfloat16(a4[2*rr]   - __bfloat162float(h0));
                    __nv_bfloat16 l1 = __float2bfloat16(a4[2*rr+1] - __bfloat162float(h1));
                    *(uint32_t*)&Chg[o] = pack2bf(h0, h1);
                    *(uint32_t*)&Clg[o] = pack2bf(l0, l1);
                }
            } else if (trans) {
                float* Cb = C + (size_t)z * cStr;
                Cb[(size_t)(c + 0)*Tt + r0]     = a4[0];
                Cb[(size_t)(c + 1)*Tt + r0]     = a4[1];
                Cb[(size_t)(c + 0)*Tt + r0 + 8] = a4[2];
                Cb[(size_t)(c + 1)*Tt + r0 + 8] = a4[3];
            } else {
                float* Cb = C + (size_t)z * cStr;
                *(float2*)&Cb[(size_t)r0*N + c]       = make_float2(a4[0], a4[1]);
                *(float2*)&Cb[(size_t)(r0 + 8)*N + c] = make_float2(a4[2], a4[3]);
            }
        }
    }
}

// ======== tensor-core dual NT GEMM: Sb = pb@q^T, Sd = tanh((p*Wd)@q^T)*vd ====
// M=128 (p rows), N=64 (q rows), K=768. A tiles [m][k]; B tile (q) [n][k].
__global__ void __launch_bounds__(256, 2) gemm_bt2t(const float* __restrict__ vd) {
    __shared__ __nv_bfloat16 A1h[128][40], A1l[128][40];  // pb
    __shared__ __nv_bfloat16 A2h[128][40], A2l[128][40];  // pd = p*Wd
    __shared__ __nv_bfloat16 Bqh[64][40],  Bql[64][40];   // q (n-major, k-contig)

    int b = blockIdx.z;
    int m0 = blockIdx.y * 128, n0 = blockIdx.x * 64;
    size_t pbase = (size_t)b*Tt*Hh;

    int tid = threadIdx.x;
    int wid = tid >> 5, l = tid & 31;
    int moff = (wid & 3) * 32;        // 2 x m16 tiles
    int noff = (wid >> 2) * 32;       // 4 x n8 tiles

    uint32_t a1hB = smem_u32(A1h), a1lB = smem_u32(A1l);
    uint32_t a2hB = smem_u32(A2h), a2lB = smem_u32(A2l);
    uint32_t bhB  = smem_u32(Bqh), blB  = smem_u32(Bql);

    uint32_t aOff[2], bOff[2];
    #pragma unroll
    for (int mt = 0; mt < 2; mt++)
        aOff[mt] = ((moff + mt*16 + (l & 15))*40 + (l >> 4)*8) * 2;
    #pragma unroll
    for (int ng = 0; ng < 2; ng++)
        bOff[ng] = ((noff + ng*16 + ((l >> 4) << 3) + (l & 7))*40 + ((l >> 3) & 1)*8) * 2;

    float accB[2][4][4] = {}, accD[2][4][4] = {};

    for (int k0 = 0; k0 < Hh; k0 += 32) {
        #pragma unroll
        for (int i = 0; i < 2; i++) {
            int idx = tid + i*256;
            int row = idx >> 2, seg = idx & 3;
            size_t g = pbase + (size_t)(m0 + row)*Hh + k0 + seg*8;
            *(uint4*)&A1h[row][seg*8] = *(const uint4*)&g_pbh[g];
            *(uint4*)&A1l[row][seg*8] = *(const uint4*)&g_pbl[g];
            *(uint4*)&A2h[row][seg*8] = *(const uint4*)&g_pdh[g];
            *(uint4*)&A2l[row][seg*8] = *(const uint4*)&g_pdl[g];
        }
        {
            int row = tid >> 2, seg = tid & 3;     // 64 rows x 4 segs
            size_t g = pbase + (size_t)(n0 + row)*Hh + k0 + seg*8;
            *(uint4*)&Bqh[row][seg*8] = *(const uint4*)&g_qh[g];
            *(uint4*)&Bql[row][seg*8] = *(const uint4*)&g_ql[g];
        }
        __syncthreads();

        #pragma unroll
        for (int kk = 0; kk < 2; kk++) {
            uint32_t bh[2][4], bl[2][4];
            #pragma unroll
            for (int ng = 0; ng < 2; ng++) {
                uint32_t bo = bOff[ng] + kk*32;
                ldsm4(bh[ng], bhB + bo);
                ldsm4(bl[ng], blB + bo);
            }
            #pragma unroll
            for (int mt = 0; mt < 2; mt++) {
                uint32_t ah[4], al[4];
                uint32_t ao = aOff[mt] + kk*32;
                ldsm4(ah, a1hB + ao);
                ldsm4(al, a1lB + ao);
                #pragma unroll
                for (int ng = 0; ng < 2; ng++) {
                    mma16816(accB[mt][2*ng],   ah, bh[ng][0], bh[ng][1]);
                    mma16816(accB[mt][2*ng],   ah, bl[ng][0], bl[ng][1]);
                    mma16816(accB[mt][2*ng],   al, bh[ng][0], bh[ng][1]);
                    mma16816(accB[mt][2*ng+1], ah, bh[ng][2], bh[ng][3]);
                    mma16816(accB[mt][2*ng+1], ah, bl[ng][2], bl[ng][3]);
                    mma16816(accB[mt][2*ng+1], al, bh[ng][2], bh[ng][3]);
                }
            }
            #pragma unroll
            for (int mt = 0; mt < 2; mt++) {
                uint32_t ah[4], al[4];
                uint32_t ao = aOff[mt] + kk*32;
                ldsm4(ah, a2hB + ao);
                ldsm4(al, a2lB + ao);
                #pragma unroll
                for (int ng = 0; ng < 2; ng++) {
                    mma16816(accD[mt][2*ng],   ah, bh[ng][0], bh[ng][1]);
                    mma16816(accD[mt][2*ng],   ah, bl[ng][0], bl[ng][1]);
                    mma16816(accD[mt][2*ng],   al, bh[ng][0], bh[ng][1]);
                    mma16816(accD[mt][2*ng+1], ah, bh[ng][2], bh[ng][3]);
                    mma16816(accD[mt][2*ng+1], ah, bl[ng][2], bl[ng][3]);
                    mma16816(accD[mt][2*ng+1], al, bh[ng][2], bh[ng][3]);
                }
            }
        }
        __syncthreads();
    }

    size_t sbase = (size_t)b*Tt*Tt;
    int lr = l >> 2, lc = l & 3;
    #pragma unroll
    for (int mt = 0; mt < 2; mt++) {
        int r0 = m0 + moff + mt*16 + lr;
        #pragma unroll
        for (int nt = 0; nt < 4; nt++) {
            int c = n0 + noff + nt*8 + 2*lc;
            float vd0 = vd[c], vd1 = vd[c + 1];
            #pragma unroll
            for (int rr = 0; rr < 2; rr++) {
                size_t o = sbase + (size_t)(r0 + rr*8)*Tt + c;
                *(float2*)&g_Sb[o] = make_float2(accB[mt][nt][2*rr], accB[mt][nt][2*rr+1]);
                g_Sd[o + 0] = tanhf(accD[mt][nt][2*rr])   * vd0;
                g_Sd[o + 1] = tanhf(accD[mt][nt][2*rr+1]) * vd1;
            }
        }
    }
}

// ---------------- K3: finish scores + row softmax -> bf16 hi/lo P ------------
__global__ void k_softmax(const float* __restrict__ vc, const float* __restrict__ vm) {
    int mode = blockIdx.z, b = blockIdx.y, i = blockIdx.x, j = threadIdx.x;
    size_t base = (size_t)b*Tt*Tt + (size_t)i*Tt;
    float s;
    if      (mode == 0) s = tanhf(g_whp[base + j] + g_whqT[base + j]) * vc[i];
    else if (mode == 1) s = g_Sb[base + j];
    else if (mode == 2) s = g_Sd[base + j];
    else                s = tanhf(g_qWm[b*Tt + j] - g_pWm[b*Tt + i]) * vm[j];

    float m = s;
    for (int o = 16; o; o >>= 1) m = fmaxf(m, __shfl_xor_sync(0xffffffffu, m, o));
    __shared__ float rm[8], rs[8];
    int w = j >> 5, l = j & 31;
    if (!l) rm[w] = m;
    __syncthreads();
    float mm = rm[0];
    #pragma unroll
    for (int k = 1; k < 8; k++) mm = fmaxf(mm, rm[k]);

    float e = __expf(s - mm);
    float sum = e;
    for (int o = 16; o; o >>= 1) sum += __shfl_xor_sync(0xffffffffu, sum, o);
    if (!l) rs[w] = sum;
    __syncthreads();
    float tot = 0.f;
    #pragma unroll
    for (int k = 0; k < 8; k++) tot += rs[k];

    float prob = e / tot;
    size_t idx = (size_t)mode*Bb*Tt*Tt + base + j;
    __nv_bfloat16 h = __float2bfloat16(prob);
    g_Ph[idx] = h;
    g_Pl[idx] = __float2bfloat16(prob - __bfloat162float(h));
}

// ---------------- launch -----------------------------------------------------
extern "C" void kernel_launch(void* const* d_in, const int* in_sizes, int n_in,
                              void* d_out, int out_size) {
    const float* q   = (const float*)d_in[0];
    const float* p   = (const float*)d_in[1];
    const float* Wc1 = (const float*)d_in[2];
    const float* Wc2 = (const float*)d_in[3];
    const float* vc  = (const float*)d_in[4];
    const float* Wb  = (const float*)d_in[5];
    const float* Wd  = (const float*)d_in[6];
    const float* vd  = (const float*)d_in[7];
    const float* Wm  = (const float*)d_in[8];
    const float* vm  = (const float*)d_in[9];
    float* out = (float*)d_out;

    float* d_whqT; cudaGetSymbolAddress((void**)&d_whqT, g_whqT);
    float* d_whp;  cudaGetSymbolAddress((void**)&d_whp,  g_whp);
    __nv_bfloat16 *d_qh, *d_ql, *d_ph, *d_pl, *d_W1h, *d_W1l, *d_W2h, *d_W2l;
    __nv_bfloat16 *d_Wbh, *d_Wbl, *d_Ph, *d_Pl, *d_pbh, *d_pbl, *d_pdh, *d_pdl;
    cudaGetSymbolAddress((void**)&d_qh, g_qh);   cudaGetSymbolAddress((void**)&d_ql, g_ql);
    cudaGetSymbolAddress((void**)&d_ph, g_ph);   cudaGetSymbolAddress((void**)&d_pl, g_pl);
    cudaGetSymbolAddress((void**)&d_W1h, g_W1h); cudaGetSymbolAddress((void**)&d_W1l, g_W1l);
    cudaGetSymbolAddress((void**)&d_W2h, g_W2h); cudaGetSymbolAddress((void**)&d_W2l, g_W2l);
    cudaGetSymbolAddress((void**)&d_Wbh, g_Wbh); cudaGetSymbolAddress((void**)&d_Wbl, g_Wbl);
    cudaGetSymbolAddress((void**)&d_Ph, g_Ph);   cudaGetSymbolAddress((void**)&d_Pl, g_Pl);
    cudaGetSymbolAddress((void**)&d_pbh, g_pbh); cudaGetSymbolAddress((void**)&d_pbl, g_pbl);
    cudaGetSymbolAddress((void**)&d_pdh, g_pdh); cudaGetSymbolAddress((void**)&d_pdl, g_pdl);

    const int nQP8 = Bb*Tt*Hh/8;
    k_cvt<<<(nQP8 + 255)/256, 256>>>(q, d_qh, d_ql, nQP8);
    k_cvt<<<(nQP8 + 255)/256, 256>>>(p, d_ph, d_pl, nQP8);
    k_cvt_wd<<<(nQP8 + 255)/256, 256>>>(p, Wd, d_pdh, d_pdl, nQP8);
    k_cvt<<<(Hh*Tt/8 + 255)/256, 256>>>(Wc1, d_W1h, d_W1l, Hh*Tt/8);
    k_cvt<<<(Hh*Tt/8 + 255)/256, 256>>>(Wc2, d_W2h, d_W2l, Hh*Tt/8);
    k_cvt<<<(Hh*Hh/8 + 255)/256, 256>>>(Wb, d_Wbh, d_Wbl, Hh*Hh/8);

    k_vec<<<dim3(Tt, Bb), 256>>>(q, p, Wm);
    // whqT[b] = (q[b] @ Wc1) stored transposed (fp32)
    gemm128t<<<dim3(2, 2, Bb), 256>>>(d_qh, d_ql, (size_t)Tt*Hh, Hh,
                                      d_W1h, d_W1l, 0, 0, Tt,
                                      d_whqT, nullptr, nullptr, (size_t)Tt*Tt, Hh, 1);
    // whp[b] = p[b] @ Wc2 (fp32)
    gemm128t<<<dim3(2, 2, Bb), 256>>>(d_ph, d_pl, (size_t)Tt*Hh, Hh,
                                      d_W2h, d_W2l, 0, 0, Tt,
                                      d_whp, nullptr, nullptr, (size_t)Tt*Tt, Hh, 0);
    // pb[b] = p[b] @ Wb  -> bf16 hi/lo directly
    gemm128t<<<dim3(6, 2, Bb), 256>>>(d_ph, d_pl, (size_t)Tt*Hh, Hh,
                                      d_Wbh, d_Wbl, 0, 0, Hh,
                                      nullptr, d_pbh, d_pbl, (size_t)Tt*Hh, Hh, 0);
    // Sb, Sd via tensor cores
    gemm_bt2t<<<dim3(4, 2, Bb), 256>>>(vd);
    // 4x softmax -> Ph/Pl
    k_softmax<<<dim3(Tt, Bb, 4), 256>>>(vc, vm);
    // out[z] = P[z] @ q[z&63] (fp32), K = Tt (FIX: was Hh -> OOB)
    gemm128t<<<dim3(6, 2, 4*Bb), 256>>>(d_Ph, d_Pl, (size_t)Tt*Tt, Tt,
                                        d_qh, d_ql, (size_t)Tt*Hh, 63, Hh,
                                        out, nullptr, nullptr, (size_t)Tt*Hh, Tt, 0);
}